// round 10
// baseline (speedup 1.0000x reference)
#include <cuda_runtime.h>
#include <cuda_bf16.h>
#include <math.h>
#include <stdint.h>

// Problem constants: B=2, L=256, d_e=d_h=512
#define DH   512
#define LSEQ 256
#define MTOT 512   // B*L rows

// ---------------- scratch (no allocations allowed) ----------------
__device__ __align__(16) float g_rep  [MTOT*DH];
__device__ __align__(16) float g_dep2 [MTOT*DH];   // (dep + w1_b + b_logit) * KC
__device__ __align__(16) float g_head2[MTOT*DH];   // (head + w2_b) * KC
__device__ __align__(16) float g_gate1[MTOT*DH];   // rep @ wf1
__device__ __align__(16) float g_attn [MTOT*DH];

// bf16 split operands
__device__ __align__(16) __nv_bfloat16 g_Wthi[5 * DH * DH];  // W^T hi, [N,K] K-major
__device__ __align__(16) __nv_bfloat16 g_Wtlo[5 * DH * DH];
__device__ __align__(16) __nv_bfloat16 g_xhi[MTOT * DH];     // x split (gemm0 A)
__device__ __align__(16) __nv_bfloat16 g_xlo[MTOT * DH];
__device__ __align__(16) __nv_bfloat16 g_Ahi[MTOT * DH];     // rep split, then attn split
__device__ __align__(16) __nv_bfloat16 g_Alo[MTOT * DH];

// ---------------- math helpers ----------------
__device__ __forceinline__ float ex2f(float x) {
    float r; asm("ex2.approx.f32 %0, %1;" : "=f"(r) : "f"(x)); return r;
}
__device__ __forceinline__ float rcpf(float x) {
    float r; asm("rcp.approx.f32 %0, %1;" : "=f"(r) : "f"(x)); return r;
}
#define KCNST  (-0.57707801635558536f)   // -2*log2e/5
#define C2CNST (7.2134752044448170f)     // 5*log2e
#define TWOC2  (14.426950408889634f)

__device__ __forceinline__ void split_bf16(float v, __nv_bfloat16 &hi, __nv_bfloat16 &lo) {
    hi = __float2bfloat16(v);
    lo = __float2bfloat16(v - __bfloat162float(hi));
}

// ---------------- cp.async + mma.sync (sm_80 path, legal on sm_100) ----
__device__ __forceinline__ uint32_t smem_u32(const void* p) {
    uint32_t a;
    asm("{ .reg .u64 t; cvta.to.shared.u64 t, %1; cvt.u32.u64 %0, t; }" : "=r"(a) : "l"(p));
    return a;
}
__device__ __forceinline__ void cp_async16(uint32_t saddr, const void* g) {
    asm volatile("cp.async.cg.shared.global [%0], [%1], 16;" :: "r"(saddr), "l"(g) : "memory");
}
__device__ __forceinline__ void cp_commit() {
    asm volatile("cp.async.commit_group;" ::: "memory");
}
__device__ __forceinline__ void cp_wait0() {
    asm volatile("cp.async.wait_group 0;" ::: "memory");
}
// m16n8k16 row.col bf16 -> f32 accumulate
__device__ __forceinline__ void mma_bf16(float* d, const uint32_t* a, const uint32_t* b) {
    asm volatile(
        "mma.sync.aligned.m16n8k16.row.col.f32.bf16.bf16.f32 "
        "{%0,%1,%2,%3}, {%4,%5,%6,%7}, {%8,%9}, {%0,%1,%2,%3};"
        : "+f"(d[0]), "+f"(d[1]), "+f"(d[2]), "+f"(d[3])
        : "r"(a[0]), "r"(a[1]), "r"(a[2]), "r"(a[3]), "r"(b[0]), "r"(b[1]));
}

// =====================================================================
// Pre-pass: z<5: transpose + bf16-split weight z.
//           z=5: bf16-split x (no transpose).
// W [K=512, N=512] fp32 row-major -> Wt_hi/lo [N, K] bf16 K-major.
// =====================================================================
__global__ void __launch_bounds__(256) prep_kernel(
    const float* __restrict__ w0, const float* __restrict__ w1,
    const float* __restrict__ w2, const float* __restrict__ w3,
    const float* __restrict__ w4, const float* __restrict__ x)
{
    __shared__ float t[32][33];
    const int z = blockIdx.z;
    const int bi = blockIdx.x;
    const int bj = blockIdx.y;
    const int r  = threadIdx.x >> 3;
    const int c4 = (threadIdx.x & 7) * 4;

    if (z == 5) {   // split x, same layout
        const size_t gi = (size_t)(bi * 32 + r) * DH + bj * 32 + c4;
        const float4 v = *(const float4*)&x[gi];
        __nv_bfloat16 h, l;
        split_bf16(v.x, h, l); g_xhi[gi]     = h; g_xlo[gi]     = l;
        split_bf16(v.y, h, l); g_xhi[gi + 1] = h; g_xlo[gi + 1] = l;
        split_bf16(v.z, h, l); g_xhi[gi + 2] = h; g_xlo[gi + 2] = l;
        split_bf16(v.w, h, l); g_xhi[gi + 3] = h; g_xlo[gi + 3] = l;
        return;
    }

    const float* W = (z == 0) ? w0 : (z == 1) ? w1 : (z == 2) ? w2 : (z == 3) ? w3 : w4;
    const float4 v = *(const float4*)&W[(bi * 32 + r) * DH + bj * 32 + c4];
    t[r][c4 + 0] = v.x; t[r][c4 + 1] = v.y; t[r][c4 + 2] = v.z; t[r][c4 + 3] = v.w;
    __syncthreads();

    const size_t base = (size_t)z * DH * DH + (size_t)(bj * 32 + r) * DH + bi * 32 + c4;
    #pragma unroll
    for (int i = 0; i < 4; ++i) {
        const float a = t[c4 + i][r];
        __nv_bfloat16 hi, lo; split_bf16(a, hi, lo);
        g_Wthi[base + i] = hi;
        g_Wtlo[base + i] = lo;
    }
}

// =====================================================================
// mma.sync GEMM: CTA tile 32 x TN (TN=32 everywhere now),
// 4 warps, warp tile 32 x (TN/4) = 2 x (TN/32) m16n8k16 atoms.
// K=512 in 8 chunks of 64, double-buffered cp.async, scalar LDS frags.
// Split-bf16 3-pass: hi*hi + hi*lo + lo*hi, fp32 accumulators.
// MODE 0: A=x split,    B=Wt[0](fc),   epi: elu -> g_rep + split
// MODE 1: A=rep split,  B=Wt[1..3],    epi -> g_dep2/g_head2/g_gate1
// MODE 2: A=attn split, B=Wt[4](wf2),  epi: gate fusion -> dout
// =====================================================================
#define SROW 72                    // smem row stride in bf16 (bank padding)
#define ROWB (SROW * 2)            // 144 bytes per row

template<int MODE, int TN>
__global__ void __launch_bounds__(128) gemm_mma(
    const float* __restrict__ b0v, const float* __restrict__ b1v,
    const float* __restrict__ b2v, float* __restrict__ dout)
{
    constexpr int NAT   = TN / 32;             // n atoms per warp (1 or 2)
    constexpr int ARR_A = 32 * ROWB;           // 4608 B
    constexpr int ARR_B = TN * ROWB;
    constexpr int OFF_AL = ARR_A;
    constexpr int OFF_BH = 2 * ARR_A;
    constexpr int OFF_BL = 2 * ARR_A + ARR_B;
    constexpr int BUFB   = 2 * ARR_A + 2 * ARR_B;
    constexpr int NTXN   = 512 + TN * 16;      // 16B txns per chunk
    constexpr int NT_PER_W = DH / TN;          // n-tiles per weight

    extern __shared__ char sm[];
    const uint32_t sbase = smem_u32(sm);
    const int tid  = threadIdx.x;
    const int warp = tid >> 5, lane = tid & 31;
    const int grp  = lane >> 2, tig = lane & 3;
    const int wn   = warp * (TN / 4);          // warp N offset

    const int m0 = blockIdx.x * 32;
    int n0, widx, region = 0;
    if (MODE == 1) {
        region = blockIdx.y / NT_PER_W;
        n0 = (blockIdx.y % NT_PER_W) * TN;
        widx = 1 + region;
    } else {
        n0 = blockIdx.y * TN; widx = (MODE == 0) ? 0 : 4;
    }

    const __nv_bfloat16* __restrict__ Ah = (MODE == 0) ? g_xhi : g_Ahi;
    const __nv_bfloat16* __restrict__ Al = (MODE == 0) ? g_xlo : g_Alo;
    const __nv_bfloat16* __restrict__ Bh = g_Wthi + (size_t)widx * DH * DH;
    const __nv_bfloat16* __restrict__ Bl = g_Wtlo + (size_t)widx * DH * DH;

    // ---- async loader: chunk c (64 k) into buffer buf ----
    auto issue = [&](int c, int buf) {
        #pragma unroll
        for (int i = 0; i < NTXN / 128; ++i) {
            const int idx = tid + i * 128;
            const __nv_bfloat16* gp;
            uint32_t sa;
            if (idx < 512) {                       // A: Ah then Al, 256 txns each
                const int arr = idx >> 8;          // 0:Ah 1:Al
                const int row = (idx & 255) >> 3;
                const int kv  = (idx & 7) * 8;
                gp = (arr == 0 ? Ah : Al) + (size_t)(m0 + row) * DH + c * 64 + kv;
                sa = sbase + buf * BUFB + arr * OFF_AL + row * ROWB + kv * 2;
            } else {                               // B: Bh then Bl, TN*8 txns each
                const int j   = idx - 512;
                const int arr = j / (TN * 8);      // 0:Bh 1:Bl
                const int rj  = j - arr * (TN * 8);
                const int row = rj >> 3;
                const int kv  = (rj & 7) * 8;
                gp = (arr == 0 ? Bh : Bl) + (size_t)(n0 + row) * DH + c * 64 + kv;
                sa = sbase + buf * BUFB + (arr == 0 ? OFF_BH : OFF_BL) + row * ROWB + kv * 2;
            }
            cp_async16(sa, gp);
        }
        cp_commit();
    };

    float acc[2][NAT][4] = {};   // [matom][natom][reg]

    auto compute = [&](int buf) {
        const char* base = sm + buf * BUFB;
        const char* A0 = base;
        const char* A1 = base + OFF_AL;
        const char* B0 = base + OFF_BH;
        const char* B1 = base + OFF_BL;
        #pragma unroll
        for (int ks = 0; ks < 4; ++ks) {
            const int kb = ks * 16 + 2 * tig;
            uint32_t ah[2][4], al[2][4], bh[NAT][2], bl[NAT][2];
            #pragma unroll
            for (int ma = 0; ma < 2; ++ma) {
                const int r = ma * 16 + grp;
                ah[ma][0] = *(const uint32_t*)(A0 + r * ROWB + kb * 2);
                ah[ma][1] = *(const uint32_t*)(A0 + (r + 8) * ROWB + kb * 2);
                ah[ma][2] = *(const uint32_t*)(A0 + r * ROWB + (kb + 8) * 2);
                ah[ma][3] = *(const uint32_t*)(A0 + (r + 8) * ROWB + (kb + 8) * 2);
                al[ma][0] = *(const uint32_t*)(A1 + r * ROWB + kb * 2);
                al[ma][1] = *(const uint32_t*)(A1 + (r + 8) * ROWB + kb * 2);
                al[ma][2] = *(const uint32_t*)(A1 + r * ROWB + (kb + 8) * 2);
                al[ma][3] = *(const uint32_t*)(A1 + (r + 8) * ROWB + (kb + 8) * 2);
            }
            #pragma unroll
            for (int nb = 0; nb < NAT; ++nb) {
                const int r = wn + nb * 8 + grp;
                bh[nb][0] = *(const uint32_t*)(B0 + r * ROWB + kb * 2);
                bh[nb][1] = *(const uint32_t*)(B0 + r * ROWB + (kb + 8) * 2);
                bl[nb][0] = *(const uint32_t*)(B1 + r * ROWB + kb * 2);
                bl[nb][1] = *(const uint32_t*)(B1 + r * ROWB + (kb + 8) * 2);
            }
            #pragma unroll
            for (int ma = 0; ma < 2; ++ma)
                #pragma unroll
                for (int nb = 0; nb < NAT; ++nb) {
                    mma_bf16(acc[ma][nb], ah[ma], bh[nb]);
                    mma_bf16(acc[ma][nb], ah[ma], bl[nb]);
                    mma_bf16(acc[ma][nb], al[ma], bh[nb]);
                }
        }
    };

    // ---- pipelined K loop ----
    issue(0, 0);
    cp_wait0();
    __syncthreads();
    #pragma unroll 1
    for (int c = 0; c < 8; ++c) {
        if (c < 7) issue(c + 1, (c + 1) & 1);
        compute(c & 1);
        if (c < 7) { cp_wait0(); __syncthreads(); }
    }

    // ---- fused epilogue ----
    #pragma unroll
    for (int ma = 0; ma < 2; ++ma) {
        #pragma unroll
        for (int nb = 0; nb < NAT; ++nb) {
            const float* d = acc[ma][nb];
            const int col = n0 + wn + nb * 8 + 2 * tig;
            #pragma unroll
            for (int half = 0; half < 2; ++half) {
                const int row = m0 + ma * 16 + grp + half * 8;
                const float v0 = d[half * 2 + 0];
                const float v1 = d[half * 2 + 1];
                const size_t idx = (size_t)row * DH + col;
                if (MODE == 0) {
                    const float s0 = v0 + b0v[col], s1 = v1 + b0v[col + 1];
                    const float r0 = s0 > 0.f ? s0 : expm1f(s0);
                    const float r1 = s1 > 0.f ? s1 : expm1f(s1);
                    g_rep[idx] = r0; g_rep[idx + 1] = r1;
                    __nv_bfloat16 h, l;
                    split_bf16(r0, h, l); g_Ahi[idx]     = h; g_Alo[idx]     = l;
                    split_bf16(r1, h, l); g_Ahi[idx + 1] = h; g_Alo[idx + 1] = l;
                } else if (MODE == 1) {
                    if (region == 0) {
                        g_dep2[idx]     = (v0 + b0v[col]     + b2v[col])     * KCNST;
                        g_dep2[idx + 1] = (v1 + b0v[col + 1] + b2v[col + 1]) * KCNST;
                    } else if (region == 1) {
                        g_head2[idx]     = (v0 + b1v[col])     * KCNST;
                        g_head2[idx + 1] = (v1 + b1v[col + 1]) * KCNST;
                    } else {
                        g_gate1[idx] = v0; g_gate1[idx + 1] = v1;
                    }
                } else {
                    const float z0 = g_gate1[idx]     + v0 + b0v[col];
                    const float z1 = g_gate1[idx + 1] + v1 + b0v[col + 1];
                    const float gg0 = 1.f / (1.f + expf(-z0));
                    const float gg1 = 1.f / (1.f + expf(-z1));
                    const float a0 = g_attn[idx], a1 = g_attn[idx + 1];
                    dout[idx]     = fmaf(gg0, g_rep[idx]     - a0, a0);
                    dout[idx + 1] = fmaf(gg1, g_rep[idx + 1] - a1, a1);
                }
            }
        }
    }
}

#define SMTOT32 (2 * (4 * 32 * ROWB))                   // 36864

// =====================================================================
// Fused masked tanh-logit softmax + weighted sum over dependents.
// grid (258, 2): blockIdx.x -> (batch, pair p), blockIdx.y -> channel half.
// p<127: rows {p, 254-p}; in the shared j-region, arg_b - arg_a = h2 - h1
//   is loop-invariant, so t_b = t_a * 2^(h2-h1): one FMUL replaces one ex2
//   (paired wfun: 5 MUFU instead of 6).
// p=127: row 127. p=128: row 255, FULLY masked: reference's logits+(-1e9)
//   round to exactly -1e9 in fp32 (ulp(1e9)=64 >> |C*tanh|<=5) -> softmax
//   exactly uniform -> attn = mean_j rep[j].
// Writes g_attn fp32 AND bf16 split into g_Ahi/g_Alo (gemm2 A operand).
// =====================================================================
__device__ __forceinline__ float wfun(float x) {
    const float t = ex2f(x);              // exp(-2u)
    const float r = rcpf(1.f + t);
    return ex2f(fmaf(TWOC2, r, -C2CNST)); // exp(C*tanh(u))
}
__device__ __forceinline__ float wfun_t(float t) {   // from precomputed t
    const float r = rcpf(1.f + t);
    return ex2f(fmaf(TWOC2, r, -C2CNST));
}
__device__ __forceinline__ void store_attn(int idx, float v) {
    g_attn[idx] = v;
    __nv_bfloat16 hi, lo; split_bf16(v, hi, lo);
    g_Ahi[idx] = hi; g_Alo[idx] = lo;
}

__global__ void __launch_bounds__(256) attn_kernel()
{
    const int cta = blockIdx.x;
    const int b = cta / 129;
    const int p = cta - b * 129;
    const int h = blockIdx.y * 256 + threadIdx.x;

    const float* __restrict__ dep = g_dep2  + b * LSEQ * DH;
    const float* __restrict__ hd  = g_head2 + b * LSEQ * DH;
    const float* __restrict__ rp  = g_rep   + b * LSEQ * DH;

    if (p == 128) {
        float s = 0.f;
        #pragma unroll 8
        for (int j = 0; j < LSEQ; ++j)
            s += rp[j * DH + h];
        store_attn((b * LSEQ + 255) * DH + h, s * (1.0f / 256.0f));
        return;
    }

    int i1, i2, jstart, jmid;
    if (p < 127)       { i1 = p;   i2 = 254 - p; jstart = p + 1; jmid = 255 - p; }
    else               { i1 = 127; i2 = -1;      jstart = 128;   jmid = 256; }

    const float h1 = hd[i1 * DH + h];
    const float h2 = (i2 >= 0) ? hd[i2 * DH + h] : 0.f;
    const float e2d = ex2f(h2 - h1);   // loop-invariant ratio 2^(h2-h1)

    float n1 = 0.f, d1 = 0.f, n2 = 0.f, d2 = 0.f;
    int j = jstart;
    #pragma unroll 4
    for (; j < jmid; ++j) {
        const float dj = dep[j * DH + h];
        const float rj = rp [j * DH + h];
        const float w  = wfun(dj + h1);
        n1 = fmaf(w, rj, n1); d1 += w;
    }
    #pragma unroll 4
    for (; j < 256; ++j) {
        const float dj = dep[j * DH + h];
        const float rj = rp [j * DH + h];
        const float ta = ex2f(dj + h1);
        const float wa = wfun_t(ta);
        n1 = fmaf(wa, rj, n1); d1 += wa;
        const float wb = wfun_t(ta * e2d);   // shared ex2
        n2 = fmaf(wb, rj, n2); d2 += wb;
    }
    store_attn((b * LSEQ + i1) * DH + h, n1 / d1);
    if (i2 >= 0)
        store_attn((b * LSEQ + i2) * DH + h, n2 / d2);
}

// =====================================================================
extern "C" void kernel_launch(void* const* d_in, const int* in_sizes, int n_in,
                              void* d_out, int out_size)
{
    const float* x       = (const float*)d_in[0];
    const float* fc_w    = (const float*)d_in[1];
    const float* fc_b    = (const float*)d_in[2];
    const float* w1_w    = (const float*)d_in[3];
    const float* w1_b    = (const float*)d_in[4];
    const float* w2_w    = (const float*)d_in[5];
    const float* w2_b    = (const float*)d_in[6];
    const float* b_logit = (const float*)d_in[7];
    const float* wf1_w   = (const float*)d_in[8];
    const float* wf2_w   = (const float*)d_in[9];
    const float* bf      = (const float*)d_in[10];
    float* out = (float*)d_out;

    cudaFuncSetAttribute((const void*)gemm_mma<0,32>, cudaFuncAttributeMaxDynamicSharedMemorySize, SMTOT32);
    cudaFuncSetAttribute((const void*)gemm_mma<1,32>, cudaFuncAttributeMaxDynamicSharedMemorySize, SMTOT32);
    cudaFuncSetAttribute((const void*)gemm_mma<2,32>, cudaFuncAttributeMaxDynamicSharedMemorySize, SMTOT32);

    // 0) weight transpose+split (z=0..4) and x split (z=5)
    prep_kernel<<<dim3(16, 16, 6), 256>>>(fc_w, w1_w, w2_w, wf1_w, wf2_w, x);
    // 1) rep = elu(x @ fc_w + fc_b)   (+ bf16 split of rep)  — 256 CTAs
    gemm_mma<0,32><<<dim3(16, 16), 128, SMTOT32>>>(fc_b, nullptr, nullptr, nullptr);
    // 2) dep2/head2/gate1 = rep @ {w1,w2,wf1}                — 768 CTAs
    gemm_mma<1,32><<<dim3(16, 48), 128, SMTOT32>>>(w1_b, w2_b, b_logit, nullptr);
    // 3) fused masked softmax attention (+ bf16 split of attn)
    attn_kernel<<<dim3(258, 2), 256>>>();
    // 4) out = sigmoid(gate1 + attn@wf2 + bf) * rep + (1-g) * attn — 256 CTAs
    gemm_mma<2,32><<<dim3(16, 16), 128, SMTOT32>>>(bf, nullptr, nullptr, out);
}

// round 11
// speedup vs baseline: 1.2940x; 1.2940x over previous
#include <cuda_runtime.h>
#include <cuda_bf16.h>
#include <math.h>
#include <stdint.h>

// Problem constants: B=2, L=256, d_e=d_h=512
#define DH   512
#define LSEQ 256
#define MTOT 512   // B*L rows

// ---------------- scratch (no allocations allowed) ----------------
__device__ __align__(16) float  g_rep  [MTOT*DH];
__device__ __align__(16) float2 g_dr   [MTOT*DH];   // (dep', rep) packed; dep' = (dep+w1_b+b_logit)/C
__device__ __align__(16) float  g_head2[MTOT*DH];   // (head + w2_b)/C
__device__ __align__(16) float  g_gate1[MTOT*DH];   // rep @ wf1
__device__ __align__(16) float  g_attn [MTOT*DH];

// bf16 split operands
__device__ __align__(16) __nv_bfloat16 g_Wthi[5 * DH * DH];  // W^T hi, [N,K] K-major
__device__ __align__(16) __nv_bfloat16 g_Wtlo[5 * DH * DH];
__device__ __align__(16) __nv_bfloat16 g_xhi[MTOT * DH];     // x split (gemm0 A)
__device__ __align__(16) __nv_bfloat16 g_xlo[MTOT * DH];
__device__ __align__(16) __nv_bfloat16 g_Ahi[MTOT * DH];     // rep split, then attn split
__device__ __align__(16) __nv_bfloat16 g_Alo[MTOT * DH];

// ---------------- math helpers ----------------
__device__ __forceinline__ float ex2f(float x) {
    float r; asm("ex2.approx.f32 %0, %1;" : "=f"(r) : "f"(x)); return r;
}
__device__ __forceinline__ float tanh_ap(float x) {
    float r; asm("tanh.approx.f32 %0, %1;" : "=f"(r) : "f"(x)); return r;
}
#define INVC   0.2f                      // 1/C
#define C2CNST (7.2134752044448170f)     // C*log2e = 5*log2(e)

__device__ __forceinline__ void split_bf16(float v, __nv_bfloat16 &hi, __nv_bfloat16 &lo) {
    hi = __float2bfloat16(v);
    lo = __float2bfloat16(v - __bfloat162float(hi));
}

// ---------------- cp.async + mma.sync (sm_80 path, legal on sm_100) ----
__device__ __forceinline__ uint32_t smem_u32(const void* p) {
    uint32_t a;
    asm("{ .reg .u64 t; cvta.to.shared.u64 t, %1; cvt.u32.u64 %0, t; }" : "=r"(a) : "l"(p));
    return a;
}
__device__ __forceinline__ void cp_async16(uint32_t saddr, const void* g) {
    asm volatile("cp.async.cg.shared.global [%0], [%1], 16;" :: "r"(saddr), "l"(g) : "memory");
}
__device__ __forceinline__ void cp_commit() {
    asm volatile("cp.async.commit_group;" ::: "memory");
}
__device__ __forceinline__ void cp_wait0() {
    asm volatile("cp.async.wait_group 0;" ::: "memory");
}
// m16n8k16 row.col bf16 -> f32 accumulate
__device__ __forceinline__ void mma_bf16(float* d, const uint32_t* a, const uint32_t* b) {
    asm volatile(
        "mma.sync.aligned.m16n8k16.row.col.f32.bf16.bf16.f32 "
        "{%0,%1,%2,%3}, {%4,%5,%6,%7}, {%8,%9}, {%0,%1,%2,%3};"
        : "+f"(d[0]), "+f"(d[1]), "+f"(d[2]), "+f"(d[3])
        : "r"(a[0]), "r"(a[1]), "r"(a[2]), "r"(a[3]), "r"(b[0]), "r"(b[1]));
}

// =====================================================================
// Pre-pass: z<5: transpose + bf16-split weight z.  z=5: bf16-split x.
// =====================================================================
__global__ void __launch_bounds__(256) prep_kernel(
    const float* __restrict__ w0, const float* __restrict__ w1,
    const float* __restrict__ w2, const float* __restrict__ w3,
    const float* __restrict__ w4, const float* __restrict__ x)
{
    __shared__ float t[32][33];
    const int z = blockIdx.z;
    const int bi = blockIdx.x;
    const int bj = blockIdx.y;
    const int r  = threadIdx.x >> 3;
    const int c4 = (threadIdx.x & 7) * 4;

    if (z == 5) {   // split x, same layout
        const size_t gi = (size_t)(bi * 32 + r) * DH + bj * 32 + c4;
        const float4 v = *(const float4*)&x[gi];
        __nv_bfloat16 h, l;
        split_bf16(v.x, h, l); g_xhi[gi]     = h; g_xlo[gi]     = l;
        split_bf16(v.y, h, l); g_xhi[gi + 1] = h; g_xlo[gi + 1] = l;
        split_bf16(v.z, h, l); g_xhi[gi + 2] = h; g_xlo[gi + 2] = l;
        split_bf16(v.w, h, l); g_xhi[gi + 3] = h; g_xlo[gi + 3] = l;
        return;
    }

    const float* W = (z == 0) ? w0 : (z == 1) ? w1 : (z == 2) ? w2 : (z == 3) ? w3 : w4;
    const float4 v = *(const float4*)&W[(bi * 32 + r) * DH + bj * 32 + c4];
    t[r][c4 + 0] = v.x; t[r][c4 + 1] = v.y; t[r][c4 + 2] = v.z; t[r][c4 + 3] = v.w;
    __syncthreads();

    const size_t base = (size_t)z * DH * DH + (size_t)(bj * 32 + r) * DH + bi * 32 + c4;
    #pragma unroll
    for (int i = 0; i < 4; ++i) {
        const float a = t[c4 + i][r];
        __nv_bfloat16 hi, lo; split_bf16(a, hi, lo);
        g_Wthi[base + i] = hi;
        g_Wtlo[base + i] = lo;
    }
}

// =====================================================================
// mma.sync GEMM: CTA tile 32 x TN, 4 warps, warp tile 32 x (TN/4).
// K=512 in 8 chunks of 64, double-buffered cp.async, scalar LDS frags.
// Split-bf16 3-pass: hi*hi + hi*lo + lo*hi, fp32 accumulators.
// MODE 0: A=x split,    B=Wt[0](fc),   epi: elu -> g_rep + split
// MODE 1: A=rep split,  B=Wt[1..3],    epi -> g_dr (packed) /g_head2/g_gate1
// MODE 2: A=attn split, B=Wt[4](wf2),  epi: gate fusion -> dout
// =====================================================================
#define SROW 72                    // smem row stride in bf16 (bank padding)
#define ROWB (SROW * 2)            // 144 bytes per row

template<int MODE, int TN>
__global__ void __launch_bounds__(128) gemm_mma(
    const float* __restrict__ b0v, const float* __restrict__ b1v,
    const float* __restrict__ b2v, float* __restrict__ dout)
{
    constexpr int NAT   = TN / 32;             // n atoms per warp (1 or 2)
    constexpr int ARR_A = 32 * ROWB;           // 4608 B
    constexpr int ARR_B = TN * ROWB;
    constexpr int OFF_AL = ARR_A;
    constexpr int OFF_BH = 2 * ARR_A;
    constexpr int OFF_BL = 2 * ARR_A + ARR_B;
    constexpr int BUFB   = 2 * ARR_A + 2 * ARR_B;
    constexpr int NTXN   = 512 + TN * 16;      // 16B txns per chunk
    constexpr int NT_PER_W = DH / TN;          // n-tiles per weight

    extern __shared__ char sm[];
    const uint32_t sbase = smem_u32(sm);
    const int tid  = threadIdx.x;
    const int warp = tid >> 5, lane = tid & 31;
    const int grp  = lane >> 2, tig = lane & 3;
    const int wn   = warp * (TN / 4);          // warp N offset

    const int m0 = blockIdx.x * 32;
    int n0, widx, region = 0;
    if (MODE == 1) {
        region = blockIdx.y / NT_PER_W;
        n0 = (blockIdx.y % NT_PER_W) * TN;
        widx = 1 + region;
    } else {
        n0 = blockIdx.y * TN; widx = (MODE == 0) ? 0 : 4;
    }

    const __nv_bfloat16* __restrict__ Ah = (MODE == 0) ? g_xhi : g_Ahi;
    const __nv_bfloat16* __restrict__ Al = (MODE == 0) ? g_xlo : g_Alo;
    const __nv_bfloat16* __restrict__ Bh = g_Wthi + (size_t)widx * DH * DH;
    const __nv_bfloat16* __restrict__ Bl = g_Wtlo + (size_t)widx * DH * DH;

    // ---- async loader: chunk c (64 k) into buffer buf ----
    auto issue = [&](int c, int buf) {
        #pragma unroll
        for (int i = 0; i < NTXN / 128; ++i) {
            const int idx = tid + i * 128;
            const __nv_bfloat16* gp;
            uint32_t sa;
            if (idx < 512) {                       // A: Ah then Al, 256 txns each
                const int arr = idx >> 8;          // 0:Ah 1:Al
                const int row = (idx & 255) >> 3;
                const int kv  = (idx & 7) * 8;
                gp = (arr == 0 ? Ah : Al) + (size_t)(m0 + row) * DH + c * 64 + kv;
                sa = sbase + buf * BUFB + arr * OFF_AL + row * ROWB + kv * 2;
            } else {                               // B: Bh then Bl, TN*8 txns each
                const int j   = idx - 512;
                const int arr = j / (TN * 8);      // 0:Bh 1:Bl
                const int rj  = j - arr * (TN * 8);
                const int row = rj >> 3;
                const int kv  = (rj & 7) * 8;
                gp = (arr == 0 ? Bh : Bl) + (size_t)(n0 + row) * DH + c * 64 + kv;
                sa = sbase + buf * BUFB + (arr == 0 ? OFF_BH : OFF_BL) + row * ROWB + kv * 2;
            }
            cp_async16(sa, gp);
        }
        cp_commit();
    };

    float acc[2][NAT][4] = {};   // [matom][natom][reg]

    auto compute = [&](int buf) {
        const char* base = sm + buf * BUFB;
        const char* A0 = base;
        const char* A1 = base + OFF_AL;
        const char* B0 = base + OFF_BH;
        const char* B1 = base + OFF_BL;
        #pragma unroll
        for (int ks = 0; ks < 4; ++ks) {
            const int kb = ks * 16 + 2 * tig;
            uint32_t ah[2][4], al[2][4], bh[NAT][2], bl[NAT][2];
            #pragma unroll
            for (int ma = 0; ma < 2; ++ma) {
                const int r = ma * 16 + grp;
                ah[ma][0] = *(const uint32_t*)(A0 + r * ROWB + kb * 2);
                ah[ma][1] = *(const uint32_t*)(A0 + (r + 8) * ROWB + kb * 2);
                ah[ma][2] = *(const uint32_t*)(A0 + r * ROWB + (kb + 8) * 2);
                ah[ma][3] = *(const uint32_t*)(A0 + (r + 8) * ROWB + (kb + 8) * 2);
                al[ma][0] = *(const uint32_t*)(A1 + r * ROWB + kb * 2);
                al[ma][1] = *(const uint32_t*)(A1 + (r + 8) * ROWB + kb * 2);
                al[ma][2] = *(const uint32_t*)(A1 + r * ROWB + (kb + 8) * 2);
                al[ma][3] = *(const uint32_t*)(A1 + (r + 8) * ROWB + (kb + 8) * 2);
            }
            #pragma unroll
            for (int nb = 0; nb < NAT; ++nb) {
                const int r = wn + nb * 8 + grp;
                bh[nb][0] = *(const uint32_t*)(B0 + r * ROWB + kb * 2);
                bh[nb][1] = *(const uint32_t*)(B0 + r * ROWB + (kb + 8) * 2);
                bl[nb][0] = *(const uint32_t*)(B1 + r * ROWB + kb * 2);
                bl[nb][1] = *(const uint32_t*)(B1 + r * ROWB + (kb + 8) * 2);
            }
            #pragma unroll
            for (int ma = 0; ma < 2; ++ma)
                #pragma unroll
                for (int nb = 0; nb < NAT; ++nb) {
                    mma_bf16(acc[ma][nb], ah[ma], bh[nb]);
                    mma_bf16(acc[ma][nb], ah[ma], bl[nb]);
                    mma_bf16(acc[ma][nb], al[ma], bh[nb]);
                }
        }
    };

    // ---- pipelined K loop ----
    issue(0, 0);
    cp_wait0();
    __syncthreads();
    #pragma unroll 1
    for (int c = 0; c < 8; ++c) {
        if (c < 7) issue(c + 1, (c + 1) & 1);
        compute(c & 1);
        if (c < 7) { cp_wait0(); __syncthreads(); }
    }

    // ---- fused epilogue ----
    #pragma unroll
    for (int ma = 0; ma < 2; ++ma) {
        #pragma unroll
        for (int nb = 0; nb < NAT; ++nb) {
            const float* d = acc[ma][nb];
            const int col = n0 + wn + nb * 8 + 2 * tig;
            #pragma unroll
            for (int half = 0; half < 2; ++half) {
                const int row = m0 + ma * 16 + grp + half * 8;
                const float v0 = d[half * 2 + 0];
                const float v1 = d[half * 2 + 1];
                const size_t idx = (size_t)row * DH + col;
                if (MODE == 0) {
                    const float s0 = v0 + b0v[col], s1 = v1 + b0v[col + 1];
                    const float r0 = s0 > 0.f ? s0 : expm1f(s0);
                    const float r1 = s1 > 0.f ? s1 : expm1f(s1);
                    g_rep[idx] = r0; g_rep[idx + 1] = r1;
                    __nv_bfloat16 h, l;
                    split_bf16(r0, h, l); g_Ahi[idx]     = h; g_Alo[idx]     = l;
                    split_bf16(r1, h, l); g_Ahi[idx + 1] = h; g_Alo[idx + 1] = l;
                } else if (MODE == 1) {
                    if (region == 0) {
                        // packed (dep', rep): dep' = (dep + w1_b + b_logit)/C
                        g_dr[idx]     = make_float2((v0 + b0v[col]     + b2v[col])     * INVC, g_rep[idx]);
                        g_dr[idx + 1] = make_float2((v1 + b0v[col + 1] + b2v[col + 1]) * INVC, g_rep[idx + 1]);
                    } else if (region == 1) {
                        g_head2[idx]     = (v0 + b1v[col])     * INVC;
                        g_head2[idx + 1] = (v1 + b1v[col + 1]) * INVC;
                    } else {
                        g_gate1[idx] = v0; g_gate1[idx + 1] = v1;
                    }
                } else {
                    const float z0 = g_gate1[idx]     + v0 + b0v[col];
                    const float z1 = g_gate1[idx + 1] + v1 + b0v[col + 1];
                    const float gg0 = 1.f / (1.f + expf(-z0));
                    const float gg1 = 1.f / (1.f + expf(-z1));
                    const float a0 = g_attn[idx], a1 = g_attn[idx + 1];
                    dout[idx]     = fmaf(gg0, g_rep[idx]     - a0, a0);
                    dout[idx + 1] = fmaf(gg1, g_rep[idx + 1] - a1, a1);
                }
            }
        }
    }
}

#define SMTOT32 (2 * (4 * 32 * ROWB))                   // 36864
#define SMTOT64 (2 * (2 * 32 * ROWB + 2 * 64 * ROWB))   // 55296

// =====================================================================
// Fused masked tanh-logit softmax + weighted sum over dependents.
// grid (258, 2): blockIdx.x -> (batch, pair p), blockIdx.y -> channel half.
// w = exp(C*tanh(u/C)) = exp2(C*log2e * tanh.approx(v)), v = dep' + head'
//   (both pre-scaled by 1/C in the GEMM epilogue).
// (dep', rep) are loaded as one packed float2 (one LDG.64 per j).
// p<127: rows {p, 254-p}. p=127: row 127. p=128: row 255, FULLY masked:
//   reference's logits+(-1e9) round to exactly -1e9 in fp32 -> softmax
//   exactly uniform -> attn = mean_j rep[j].
// Writes g_attn fp32 AND bf16 split into g_Ahi/g_Alo (gemm2 A operand).
// =====================================================================
__device__ __forceinline__ float wtanh(float v) {
    return ex2f(C2CNST * tanh_ap(v));
}
__device__ __forceinline__ void store_attn(int idx, float v) {
    g_attn[idx] = v;
    __nv_bfloat16 hi, lo; split_bf16(v, hi, lo);
    g_Ahi[idx] = hi; g_Alo[idx] = lo;
}

__global__ void __launch_bounds__(256) attn_kernel()
{
    const int cta = blockIdx.x;
    const int b = cta / 129;
    const int p = cta - b * 129;
    const int h = blockIdx.y * 256 + threadIdx.x;

    const float2* __restrict__ dr = g_dr    + b * LSEQ * DH;
    const float*  __restrict__ hd = g_head2 + b * LSEQ * DH;

    if (p == 128) {
        float s = 0.f;
        #pragma unroll 8
        for (int j = 0; j < LSEQ; ++j)
            s += dr[j * DH + h].y;
        store_attn((b * LSEQ + 255) * DH + h, s * (1.0f / 256.0f));
        return;
    }

    int i1, i2, jstart, jmid;
    if (p < 127)       { i1 = p;   i2 = 254 - p; jstart = p + 1; jmid = 255 - p; }
    else               { i1 = 127; i2 = -1;      jstart = 128;   jmid = 256; }

    const float h1 = hd[i1 * DH + h];
    const float h2 = (i2 >= 0) ? hd[i2 * DH + h] : 0.f;

    float n1 = 0.f, d1 = 0.f, n2 = 0.f, d2 = 0.f;
    int j = jstart;
    #pragma unroll 4
    for (; j < jmid; ++j) {
        const float2 v = dr[j * DH + h];
        const float w  = wtanh(v.x + h1);
        n1 = fmaf(w, v.y, n1); d1 += w;
    }
    #pragma unroll 4
    for (; j < 256; ++j) {
        const float2 v = dr[j * DH + h];
        const float wa = wtanh(v.x + h1);
        n1 = fmaf(wa, v.y, n1); d1 += wa;
        const float wb = wtanh(v.x + h2);
        n2 = fmaf(wb, v.y, n2); d2 += wb;
    }
    store_attn((b * LSEQ + i1) * DH + h, n1 / d1);
    if (i2 >= 0)
        store_attn((b * LSEQ + i2) * DH + h, n2 / d2);
}

// =====================================================================
extern "C" void kernel_launch(void* const* d_in, const int* in_sizes, int n_in,
                              void* d_out, int out_size)
{
    const float* x       = (const float*)d_in[0];
    const float* fc_w    = (const float*)d_in[1];
    const float* fc_b    = (const float*)d_in[2];
    const float* w1_w    = (const float*)d_in[3];
    const float* w1_b    = (const float*)d_in[4];
    const float* w2_w    = (const float*)d_in[5];
    const float* w2_b    = (const float*)d_in[6];
    const float* b_logit = (const float*)d_in[7];
    const float* wf1_w   = (const float*)d_in[8];
    const float* wf2_w   = (const float*)d_in[9];
    const float* bf      = (const float*)d_in[10];
    float* out = (float*)d_out;

    cudaFuncSetAttribute((const void*)gemm_mma<0,32>, cudaFuncAttributeMaxDynamicSharedMemorySize, SMTOT32);
    cudaFuncSetAttribute((const void*)gemm_mma<1,64>, cudaFuncAttributeMaxDynamicSharedMemorySize, SMTOT64);
    cudaFuncSetAttribute((const void*)gemm_mma<2,32>, cudaFuncAttributeMaxDynamicSharedMemorySize, SMTOT32);

    // 0) weight transpose+split (z=0..4) and x split (z=5)
    prep_kernel<<<dim3(16, 16, 6), 256>>>(fc_w, w1_w, w2_w, wf1_w, wf2_w, x);
    // 1) rep = elu(x @ fc_w + fc_b)   (+ bf16 split of rep)  — 256 CTAs
    gemm_mma<0,32><<<dim3(16, 16), 128, SMTOT32>>>(fc_b, nullptr, nullptr, nullptr);
    // 2) dr/head2/gate1 = rep @ {w1,w2,wf1}                  — 384 CTAs (R9 proven)
    gemm_mma<1,64><<<dim3(16, 24), 128, SMTOT64>>>(w1_b, w2_b, b_logit, nullptr);
    // 3) fused masked softmax attention (+ bf16 split of attn)
    attn_kernel<<<dim3(258, 2), 256>>>();
    // 4) out = sigmoid(gate1 + attn@wf2 + bf) * rep + (1-g) * attn — 256 CTAs
    gemm_mma<2,32><<<dim3(16, 16), 128, SMTOT32>>>(bf, nullptr, nullptr, out);
}

// round 12
// speedup vs baseline: 1.3556x; 1.0476x over previous
#include <cuda_runtime.h>
#include <cuda_bf16.h>
#include <math.h>
#include <stdint.h>

// Problem constants: B=2, L=256, d_e=d_h=512
#define DH   512
#define LSEQ 256
#define MTOT 512   // B*L rows

// ---------------- scratch (no allocations allowed) ----------------
__device__ __align__(16) float  g_rep  [MTOT*DH];
__device__ __align__(16) float2 g_dr   [MTOT*DH];   // (dep', rep) packed; dep' = (dep+w1_b+b_logit)/C
__device__ __align__(16) float  g_head2[MTOT*DH];   // (head + w2_b)/C
__device__ __align__(16) float  g_gate1[MTOT*DH];   // rep @ wf1
__device__ __align__(16) float  g_attn [MTOT*DH];
__device__ __align__(16) float2 g_part [2][MTOT*DH]; // attention split-j partials (n, d)

// bf16 split operands
__device__ __align__(16) __nv_bfloat16 g_Wthi[5 * DH * DH];  // W^T hi, [N,K] K-major
__device__ __align__(16) __nv_bfloat16 g_Wtlo[5 * DH * DH];
__device__ __align__(16) __nv_bfloat16 g_xhi[MTOT * DH];     // x split (gemm0 A)
__device__ __align__(16) __nv_bfloat16 g_xlo[MTOT * DH];
__device__ __align__(16) __nv_bfloat16 g_Ahi[MTOT * DH];     // rep split, then attn split
__device__ __align__(16) __nv_bfloat16 g_Alo[MTOT * DH];

// ---------------- math helpers ----------------
__device__ __forceinline__ float ex2f(float x) {
    float r; asm("ex2.approx.f32 %0, %1;" : "=f"(r) : "f"(x)); return r;
}
__device__ __forceinline__ float tanh_ap(float x) {
    float r; asm("tanh.approx.f32 %0, %1;" : "=f"(r) : "f"(x)); return r;
}
#define INVC   0.2f                      // 1/C
#define C2CNST (7.2134752044448170f)     // C*log2e = 5*log2(e)

__device__ __forceinline__ void split_bf16(float v, __nv_bfloat16 &hi, __nv_bfloat16 &lo) {
    hi = __float2bfloat16(v);
    lo = __float2bfloat16(v - __bfloat162float(hi));
}

// ---------------- cp.async + mma.sync (sm_80 path, legal on sm_100) ----
__device__ __forceinline__ uint32_t smem_u32(const void* p) {
    uint32_t a;
    asm("{ .reg .u64 t; cvta.to.shared.u64 t, %1; cvt.u32.u64 %0, t; }" : "=r"(a) : "l"(p));
    return a;
}
__device__ __forceinline__ void cp_async16(uint32_t saddr, const void* g) {
    asm volatile("cp.async.cg.shared.global [%0], [%1], 16;" :: "r"(saddr), "l"(g) : "memory");
}
__device__ __forceinline__ void cp_commit() {
    asm volatile("cp.async.commit_group;" ::: "memory");
}
__device__ __forceinline__ void cp_wait0() {
    asm volatile("cp.async.wait_group 0;" ::: "memory");
}
// m16n8k16 row.col bf16 -> f32 accumulate
__device__ __forceinline__ void mma_bf16(float* d, const uint32_t* a, const uint32_t* b) {
    asm volatile(
        "mma.sync.aligned.m16n8k16.row.col.f32.bf16.bf16.f32 "
        "{%0,%1,%2,%3}, {%4,%5,%6,%7}, {%8,%9}, {%0,%1,%2,%3};"
        : "+f"(d[0]), "+f"(d[1]), "+f"(d[2]), "+f"(d[3])
        : "r"(a[0]), "r"(a[1]), "r"(a[2]), "r"(a[3]), "r"(b[0]), "r"(b[1]));
}

// =====================================================================
// Pre-pass: z<5: transpose + bf16-split weight z.  z=5: bf16-split x.
// =====================================================================
__global__ void __launch_bounds__(256) prep_kernel(
    const float* __restrict__ w0, const float* __restrict__ w1,
    const float* __restrict__ w2, const float* __restrict__ w3,
    const float* __restrict__ w4, const float* __restrict__ x)
{
    __shared__ float t[32][33];
    const int z = blockIdx.z;
    const int bi = blockIdx.x;
    const int bj = blockIdx.y;
    const int r  = threadIdx.x >> 3;
    const int c4 = (threadIdx.x & 7) * 4;

    if (z == 5) {   // split x, same layout
        const size_t gi = (size_t)(bi * 32 + r) * DH + bj * 32 + c4;
        const float4 v = *(const float4*)&x[gi];
        __nv_bfloat16 h, l;
        split_bf16(v.x, h, l); g_xhi[gi]     = h; g_xlo[gi]     = l;
        split_bf16(v.y, h, l); g_xhi[gi + 1] = h; g_xlo[gi + 1] = l;
        split_bf16(v.z, h, l); g_xhi[gi + 2] = h; g_xlo[gi + 2] = l;
        split_bf16(v.w, h, l); g_xhi[gi + 3] = h; g_xlo[gi + 3] = l;
        return;
    }

    const float* W = (z == 0) ? w0 : (z == 1) ? w1 : (z == 2) ? w2 : (z == 3) ? w3 : w4;
    const float4 v = *(const float4*)&W[(bi * 32 + r) * DH + bj * 32 + c4];
    t[r][c4 + 0] = v.x; t[r][c4 + 1] = v.y; t[r][c4 + 2] = v.z; t[r][c4 + 3] = v.w;
    __syncthreads();

    const size_t base = (size_t)z * DH * DH + (size_t)(bj * 32 + r) * DH + bi * 32 + c4;
    #pragma unroll
    for (int i = 0; i < 4; ++i) {
        const float a = t[c4 + i][r];
        __nv_bfloat16 hi, lo; split_bf16(a, hi, lo);
        g_Wthi[base + i] = hi;
        g_Wtlo[base + i] = lo;
    }
}

// =====================================================================
// mma.sync GEMM: CTA tile 32 x TN, 4 warps, warp tile 32 x (TN/4).
// K=512 in 8 chunks of 64, double-buffered cp.async, scalar LDS frags.
// Split-bf16 3-pass: hi*hi + hi*lo + lo*hi, fp32 accumulators.
// MODE 0: A=x split,    B=Wt[0](fc),   epi: elu -> g_rep + split
// MODE 1: A=rep split,  B=Wt[1..3],    epi -> g_dr (packed) /g_head2/g_gate1
// MODE 2: A=attn split, B=Wt[4](wf2),  epi: gate fusion -> dout
// =====================================================================
#define SROW 72                    // smem row stride in bf16 (bank padding)
#define ROWB (SROW * 2)            // 144 bytes per row

template<int MODE, int TN>
__global__ void __launch_bounds__(128) gemm_mma(
    const float* __restrict__ b0v, const float* __restrict__ b1v,
    const float* __restrict__ b2v, float* __restrict__ dout)
{
    constexpr int NAT   = TN / 32;             // n atoms per warp (1 or 2)
    constexpr int ARR_A = 32 * ROWB;           // 4608 B
    constexpr int ARR_B = TN * ROWB;
    constexpr int OFF_AL = ARR_A;
    constexpr int OFF_BH = 2 * ARR_A;
    constexpr int OFF_BL = 2 * ARR_A + ARR_B;
    constexpr int BUFB   = 2 * ARR_A + 2 * ARR_B;
    constexpr int NTXN   = 512 + TN * 16;      // 16B txns per chunk
    constexpr int NT_PER_W = DH / TN;          // n-tiles per weight

    extern __shared__ char sm[];
    const uint32_t sbase = smem_u32(sm);
    const int tid  = threadIdx.x;
    const int warp = tid >> 5, lane = tid & 31;
    const int grp  = lane >> 2, tig = lane & 3;
    const int wn   = warp * (TN / 4);          // warp N offset

    const int m0 = blockIdx.x * 32;
    int n0, widx, region = 0;
    if (MODE == 1) {
        region = blockIdx.y / NT_PER_W;
        n0 = (blockIdx.y % NT_PER_W) * TN;
        widx = 1 + region;
    } else {
        n0 = blockIdx.y * TN; widx = (MODE == 0) ? 0 : 4;
    }

    const __nv_bfloat16* __restrict__ Ah = (MODE == 0) ? g_xhi : g_Ahi;
    const __nv_bfloat16* __restrict__ Al = (MODE == 0) ? g_xlo : g_Alo;
    const __nv_bfloat16* __restrict__ Bh = g_Wthi + (size_t)widx * DH * DH;
    const __nv_bfloat16* __restrict__ Bl = g_Wtlo + (size_t)widx * DH * DH;

    // ---- async loader: chunk c (64 k) into buffer buf ----
    auto issue = [&](int c, int buf) {
        #pragma unroll
        for (int i = 0; i < NTXN / 128; ++i) {
            const int idx = tid + i * 128;
            const __nv_bfloat16* gp;
            uint32_t sa;
            if (idx < 512) {                       // A: Ah then Al, 256 txns each
                const int arr = idx >> 8;          // 0:Ah 1:Al
                const int row = (idx & 255) >> 3;
                const int kv  = (idx & 7) * 8;
                gp = (arr == 0 ? Ah : Al) + (size_t)(m0 + row) * DH + c * 64 + kv;
                sa = sbase + buf * BUFB + arr * OFF_AL + row * ROWB + kv * 2;
            } else {                               // B: Bh then Bl, TN*8 txns each
                const int j   = idx - 512;
                const int arr = j / (TN * 8);      // 0:Bh 1:Bl
                const int rj  = j - arr * (TN * 8);
                const int row = rj >> 3;
                const int kv  = (rj & 7) * 8;
                gp = (arr == 0 ? Bh : Bl) + (size_t)(n0 + row) * DH + c * 64 + kv;
                sa = sbase + buf * BUFB + (arr == 0 ? OFF_BH : OFF_BL) + row * ROWB + kv * 2;
            }
            cp_async16(sa, gp);
        }
        cp_commit();
    };

    float acc[2][NAT][4] = {};   // [matom][natom][reg]

    auto compute = [&](int buf) {
        const char* base = sm + buf * BUFB;
        const char* A0 = base;
        const char* A1 = base + OFF_AL;
        const char* B0 = base + OFF_BH;
        const char* B1 = base + OFF_BL;
        #pragma unroll
        for (int ks = 0; ks < 4; ++ks) {
            const int kb = ks * 16 + 2 * tig;
            uint32_t ah[2][4], al[2][4], bh[NAT][2], bl[NAT][2];
            #pragma unroll
            for (int ma = 0; ma < 2; ++ma) {
                const int r = ma * 16 + grp;
                ah[ma][0] = *(const uint32_t*)(A0 + r * ROWB + kb * 2);
                ah[ma][1] = *(const uint32_t*)(A0 + (r + 8) * ROWB + kb * 2);
                ah[ma][2] = *(const uint32_t*)(A0 + r * ROWB + (kb + 8) * 2);
                ah[ma][3] = *(const uint32_t*)(A0 + (r + 8) * ROWB + (kb + 8) * 2);
                al[ma][0] = *(const uint32_t*)(A1 + r * ROWB + kb * 2);
                al[ma][1] = *(const uint32_t*)(A1 + (r + 8) * ROWB + kb * 2);
                al[ma][2] = *(const uint32_t*)(A1 + r * ROWB + (kb + 8) * 2);
                al[ma][3] = *(const uint32_t*)(A1 + (r + 8) * ROWB + (kb + 8) * 2);
            }
            #pragma unroll
            for (int nb = 0; nb < NAT; ++nb) {
                const int r = wn + nb * 8 + grp;
                bh[nb][0] = *(const uint32_t*)(B0 + r * ROWB + kb * 2);
                bh[nb][1] = *(const uint32_t*)(B0 + r * ROWB + (kb + 8) * 2);
                bl[nb][0] = *(const uint32_t*)(B1 + r * ROWB + kb * 2);
                bl[nb][1] = *(const uint32_t*)(B1 + r * ROWB + (kb + 8) * 2);
            }
            #pragma unroll
            for (int ma = 0; ma < 2; ++ma)
                #pragma unroll
                for (int nb = 0; nb < NAT; ++nb) {
                    mma_bf16(acc[ma][nb], ah[ma], bh[nb]);
                    mma_bf16(acc[ma][nb], ah[ma], bl[nb]);
                    mma_bf16(acc[ma][nb], al[ma], bh[nb]);
                }
        }
    };

    // ---- pipelined K loop ----
    issue(0, 0);
    cp_wait0();
    __syncthreads();
    #pragma unroll 1
    for (int c = 0; c < 8; ++c) {
        if (c < 7) issue(c + 1, (c + 1) & 1);
        compute(c & 1);
        if (c < 7) { cp_wait0(); __syncthreads(); }
    }

    // ---- fused epilogue ----
    #pragma unroll
    for (int ma = 0; ma < 2; ++ma) {
        #pragma unroll
        for (int nb = 0; nb < NAT; ++nb) {
            const float* d = acc[ma][nb];
            const int col = n0 + wn + nb * 8 + 2 * tig;
            #pragma unroll
            for (int half = 0; half < 2; ++half) {
                const int row = m0 + ma * 16 + grp + half * 8;
                const float v0 = d[half * 2 + 0];
                const float v1 = d[half * 2 + 1];
                const size_t idx = (size_t)row * DH + col;
                if (MODE == 0) {
                    const float s0 = v0 + b0v[col], s1 = v1 + b0v[col + 1];
                    const float r0 = s0 > 0.f ? s0 : expm1f(s0);
                    const float r1 = s1 > 0.f ? s1 : expm1f(s1);
                    g_rep[idx] = r0; g_rep[idx + 1] = r1;
                    __nv_bfloat16 h, l;
                    split_bf16(r0, h, l); g_Ahi[idx]     = h; g_Alo[idx]     = l;
                    split_bf16(r1, h, l); g_Ahi[idx + 1] = h; g_Alo[idx + 1] = l;
                } else if (MODE == 1) {
                    if (region == 0) {
                        // packed (dep', rep): dep' = (dep + w1_b + b_logit)/C
                        g_dr[idx]     = make_float2((v0 + b0v[col]     + b2v[col])     * INVC, g_rep[idx]);
                        g_dr[idx + 1] = make_float2((v1 + b0v[col + 1] + b2v[col + 1]) * INVC, g_rep[idx + 1]);
                    } else if (region == 1) {
                        g_head2[idx]     = (v0 + b1v[col])     * INVC;
                        g_head2[idx + 1] = (v1 + b1v[col + 1]) * INVC;
                    } else {
                        g_gate1[idx] = v0; g_gate1[idx + 1] = v1;
                    }
                } else {
                    const float z0 = g_gate1[idx]     + v0 + b0v[col];
                    const float z1 = g_gate1[idx + 1] + v1 + b0v[col + 1];
                    const float gg0 = 1.f / (1.f + expf(-z0));
                    const float gg1 = 1.f / (1.f + expf(-z1));
                    const float a0 = g_attn[idx], a1 = g_attn[idx + 1];
                    dout[idx]     = fmaf(gg0, g_rep[idx]     - a0, a0);
                    dout[idx + 1] = fmaf(gg1, g_rep[idx + 1] - a1, a1);
                }
            }
        }
    }
}

#define SMTOT32 (2 * (4 * 32 * ROWB))                   // 36864
#define SMTOT64 (2 * (2 * 32 * ROWB + 2 * 64 * ROWB))   // 55296

// =====================================================================
// Attention, split along j (split-K for softmax):
// grid (258, 2, 2): x -> (batch, pair p), y -> j-half, z -> channel half.
// Each CTA accumulates partial (n = sum w*rep, d = sum w) for its window;
// combine kernel computes (n0+n1)/(d0+d1) and the bf16 split.
// w = exp2(C*log2e * tanh.approx(dep' + head')), operands pre-scaled 1/C.
// p<127: rows {p, 254-p}; row2 activates at j >= 255-p (clamped to window).
// p=127: row 127 only. p=128: row 255 FULLY masked -> uniform weights
//   (reference's fp32 -1e9 absorption) -> partial (sum rep, count).
// =====================================================================
__device__ __forceinline__ float wtanh(float v) {
    return ex2f(C2CNST * tanh_ap(v));
}
__device__ __forceinline__ void store_attn(int idx, float v) {
    g_attn[idx] = v;
    __nv_bfloat16 hi, lo; split_bf16(v, hi, lo);
    g_Ahi[idx] = hi; g_Alo[idx] = lo;
}

__global__ void __launch_bounds__(256) attn_part()
{
    const int cta = blockIdx.x;
    const int b = cta / 129;
    const int p = cta - b * 129;
    const int y = blockIdx.y;                      // j-half
    const int h = blockIdx.z * 256 + threadIdx.x;  // channel
    const int rb = b * LSEQ;

    const float2* __restrict__ dr = g_dr    + rb * DH;
    const float*  __restrict__ hd = g_head2 + rb * DH;

    if (p == 128) {
        // Row 255: uniform mean; partial = (sum of rep over 128 j, 128).
        float s = 0.f;
        const int j0 = y * 128;
        #pragma unroll 8
        for (int j = j0; j < j0 + 128; ++j)
            s += dr[j * DH + h].y;
        g_part[y][(rb + 255) * DH + h] = make_float2(s, 128.f);
        return;
    }

    int i1, i2, jstart, jr2;
    if (p < 127) { i1 = p;   i2 = 254 - p; jstart = p + 1; jr2 = 255 - p; }
    else         { i1 = 127; i2 = -1;      jstart = 128;   jr2 = 257; }

    const int W    = 256 - jstart;
    const int half = W >> 1;
    const int w0   = y ? (jstart + half) : jstart;
    const int w1   = y ? 256 : (jstart + half);

    const float h1 = hd[i1 * DH + h];
    const float h2 = (i2 >= 0) ? hd[i2 * DH + h] : 0.f;

    const int jb = jr2 < w0 ? w0 : (jr2 > w1 ? w1 : jr2);  // row2 activation, clamped

    float n1 = 0.f, d1 = 0.f, n2 = 0.f, d2 = 0.f;
    int j = w0;
    #pragma unroll 4
    for (; j < jb; ++j) {                 // row1 only
        const float2 v = dr[j * DH + h];
        const float w = wtanh(v.x + h1);
        n1 = fmaf(w, v.y, n1); d1 += w;
    }
    #pragma unroll 4
    for (; j < w1; ++j) {                 // both rows
        const float2 v = dr[j * DH + h];
        const float wa = wtanh(v.x + h1);
        n1 = fmaf(wa, v.y, n1); d1 += wa;
        const float wb = wtanh(v.x + h2);
        n2 = fmaf(wb, v.y, n2); d2 += wb;
    }
    g_part[y][(rb + i1) * DH + h] = make_float2(n1, d1);
    if (i2 >= 0)
        g_part[y][(rb + i2) * DH + h] = make_float2(n2, d2);
}

__global__ void __launch_bounds__(256) attn_combine()
{
    const int idx = blockIdx.x * 256 + threadIdx.x;
    const float2 a = g_part[0][idx];
    const float2 c = g_part[1][idx];
    store_attn(idx, (a.x + c.x) / (a.y + c.y));
}

// =====================================================================
extern "C" void kernel_launch(void* const* d_in, const int* in_sizes, int n_in,
                              void* d_out, int out_size)
{
    const float* x       = (const float*)d_in[0];
    const float* fc_w    = (const float*)d_in[1];
    const float* fc_b    = (const float*)d_in[2];
    const float* w1_w    = (const float*)d_in[3];
    const float* w1_b    = (const float*)d_in[4];
    const float* w2_w    = (const float*)d_in[5];
    const float* w2_b    = (const float*)d_in[6];
    const float* b_logit = (const float*)d_in[7];
    const float* wf1_w   = (const float*)d_in[8];
    const float* wf2_w   = (const float*)d_in[9];
    const float* bf      = (const float*)d_in[10];
    float* out = (float*)d_out;

    cudaFuncSetAttribute((const void*)gemm_mma<0,32>, cudaFuncAttributeMaxDynamicSharedMemorySize, SMTOT32);
    cudaFuncSetAttribute((const void*)gemm_mma<1,64>, cudaFuncAttributeMaxDynamicSharedMemorySize, SMTOT64);
    cudaFuncSetAttribute((const void*)gemm_mma<2,32>, cudaFuncAttributeMaxDynamicSharedMemorySize, SMTOT32);

    // 0) weight transpose+split (z=0..4) and x split (z=5)
    prep_kernel<<<dim3(16, 16, 6), 256>>>(fc_w, w1_w, w2_w, wf1_w, wf2_w, x);
    // 1) rep = elu(x @ fc_w + fc_b)   (+ bf16 split of rep)  — 256 CTAs
    gemm_mma<0,32><<<dim3(16, 16), 128, SMTOT32>>>(fc_b, nullptr, nullptr, nullptr);
    // 2) dr/head2/gate1 = rep @ {w1,w2,wf1}                  — 384 CTAs
    gemm_mma<1,64><<<dim3(16, 24), 128, SMTOT64>>>(w1_b, w2_b, b_logit, nullptr);
    // 3) attention partials (1032 CTAs) + combine
    attn_part<<<dim3(258, 2, 2), 256>>>();
    attn_combine<<<MTOT * DH / 256, 256>>>();
    // 4) out = sigmoid(gate1 + attn@wf2 + bf) * rep + (1-g) * attn — 256 CTAs
    gemm_mma<2,32><<<dim3(16, 16), 128, SMTOT32>>>(bf, nullptr, nullptr, out);
}

// round 13
// speedup vs baseline: 1.3708x; 1.0112x over previous
#include <cuda_runtime.h>
#include <cuda_bf16.h>
#include <math.h>
#include <stdint.h>

// Problem constants: B=2, L=256, d_e=d_h=512
#define DH   512
#define LSEQ 256
#define MTOT 512   // B*L rows

// ---------------- scratch (no allocations allowed) ----------------
__device__ __align__(16) float  g_rep  [MTOT*DH];
__device__ __align__(16) float2 g_dr   [MTOT*DH];   // (dep', rep) packed; dep' = (dep+w1_b+b_logit)/C
__device__ __align__(16) float  g_head2[MTOT*DH];   // (head + w2_b)/C
__device__ __align__(16) float  g_gate1[MTOT*DH];   // rep @ wf1
__device__ __align__(16) float  g_attn [MTOT*DH];
__device__ __align__(16) float2 g_part [4][MTOT*DH]; // attention split-j partials (n, d)

// bf16 split operands
__device__ __align__(16) __nv_bfloat16 g_Wthi[5 * DH * DH];  // W^T hi, [N,K] K-major
__device__ __align__(16) __nv_bfloat16 g_Wtlo[5 * DH * DH];
__device__ __align__(16) __nv_bfloat16 g_xhi[MTOT * DH];     // x split (gemm0 A)
__device__ __align__(16) __nv_bfloat16 g_xlo[MTOT * DH];
__device__ __align__(16) __nv_bfloat16 g_Ahi[MTOT * DH];     // rep split, then attn split
__device__ __align__(16) __nv_bfloat16 g_Alo[MTOT * DH];

// ---------------- math helpers ----------------
__device__ __forceinline__ float ex2f(float x) {
    float r; asm("ex2.approx.f32 %0, %1;" : "=f"(r) : "f"(x)); return r;
}
__device__ __forceinline__ float tanh_ap(float x) {
    float r; asm("tanh.approx.f32 %0, %1;" : "=f"(r) : "f"(x)); return r;
}
#define INVC   0.2f                      // 1/C
#define C2CNST (7.2134752044448170f)     // C*log2e = 5*log2(e)

__device__ __forceinline__ void split_bf16(float v, __nv_bfloat16 &hi, __nv_bfloat16 &lo) {
    hi = __float2bfloat16(v);
    lo = __float2bfloat16(v - __bfloat162float(hi));
}

// ---------------- cp.async + mma.sync (sm_80 path, legal on sm_100) ----
__device__ __forceinline__ uint32_t smem_u32(const void* p) {
    uint32_t a;
    asm("{ .reg .u64 t; cvta.to.shared.u64 t, %1; cvt.u32.u64 %0, t; }" : "=r"(a) : "l"(p));
    return a;
}
__device__ __forceinline__ void cp_async16(uint32_t saddr, const void* g) {
    asm volatile("cp.async.cg.shared.global [%0], [%1], 16;" :: "r"(saddr), "l"(g) : "memory");
}
__device__ __forceinline__ void cp_commit() {
    asm volatile("cp.async.commit_group;" ::: "memory");
}
__device__ __forceinline__ void cp_wait0() {
    asm volatile("cp.async.wait_group 0;" ::: "memory");
}
// m16n8k16 row.col bf16 -> f32 accumulate
__device__ __forceinline__ void mma_bf16(float* d, const uint32_t* a, const uint32_t* b) {
    asm volatile(
        "mma.sync.aligned.m16n8k16.row.col.f32.bf16.bf16.f32 "
        "{%0,%1,%2,%3}, {%4,%5,%6,%7}, {%8,%9}, {%0,%1,%2,%3};"
        : "+f"(d[0]), "+f"(d[1]), "+f"(d[2]), "+f"(d[3])
        : "r"(a[0]), "r"(a[1]), "r"(a[2]), "r"(a[3]), "r"(b[0]), "r"(b[1]));
}

// =====================================================================
// Pre-pass: z<5: transpose + bf16-split weight z.  z=5: bf16-split x.
// =====================================================================
__global__ void __launch_bounds__(256) prep_kernel(
    const float* __restrict__ w0, const float* __restrict__ w1,
    const float* __restrict__ w2, const float* __restrict__ w3,
    const float* __restrict__ w4, const float* __restrict__ x)
{
    __shared__ float t[32][33];
    const int z = blockIdx.z;
    const int bi = blockIdx.x;
    const int bj = blockIdx.y;
    const int r  = threadIdx.x >> 3;
    const int c4 = (threadIdx.x & 7) * 4;

    if (z == 5) {   // split x, same layout
        const size_t gi = (size_t)(bi * 32 + r) * DH + bj * 32 + c4;
        const float4 v = *(const float4*)&x[gi];
        __nv_bfloat16 h, l;
        split_bf16(v.x, h, l); g_xhi[gi]     = h; g_xlo[gi]     = l;
        split_bf16(v.y, h, l); g_xhi[gi + 1] = h; g_xlo[gi + 1] = l;
        split_bf16(v.z, h, l); g_xhi[gi + 2] = h; g_xlo[gi + 2] = l;
        split_bf16(v.w, h, l); g_xhi[gi + 3] = h; g_xlo[gi + 3] = l;
        return;
    }

    const float* W = (z == 0) ? w0 : (z == 1) ? w1 : (z == 2) ? w2 : (z == 3) ? w3 : w4;
    const float4 v = *(const float4*)&W[(bi * 32 + r) * DH + bj * 32 + c4];
    t[r][c4 + 0] = v.x; t[r][c4 + 1] = v.y; t[r][c4 + 2] = v.z; t[r][c4 + 3] = v.w;
    __syncthreads();

    const size_t base = (size_t)z * DH * DH + (size_t)(bj * 32 + r) * DH + bi * 32 + c4;
    #pragma unroll
    for (int i = 0; i < 4; ++i) {
        const float a = t[c4 + i][r];
        __nv_bfloat16 hi, lo; split_bf16(a, hi, lo);
        g_Wthi[base + i] = hi;
        g_Wtlo[base + i] = lo;
    }
}

// =====================================================================
// mma.sync GEMM: CTA tile 32 x TN, 4 warps, warp tile 32 x (TN/4).
// K=512 in 8 chunks of 64, double-buffered cp.async, scalar LDS frags.
// Split-bf16 3-pass: hi*hi + hi*lo + lo*hi, fp32 accumulators.
// MODE 0: A=x split,    B=Wt[0](fc),   epi: elu -> g_rep + split
// MODE 1: A=rep split,  B=Wt[1..3],    epi -> g_dr (packed) /g_head2/g_gate1
// MODE 2: A=attn split, B=Wt[4](wf2),  epi: gate fusion -> dout
// =====================================================================
#define SROW 72                    // smem row stride in bf16 (bank padding)
#define ROWB (SROW * 2)            // 144 bytes per row

template<int MODE, int TN>
__global__ void __launch_bounds__(128) gemm_mma(
    const float* __restrict__ b0v, const float* __restrict__ b1v,
    const float* __restrict__ b2v, float* __restrict__ dout)
{
    constexpr int NAT   = TN / 32;             // n atoms per warp (1 or 2)
    constexpr int ARR_A = 32 * ROWB;           // 4608 B
    constexpr int ARR_B = TN * ROWB;
    constexpr int OFF_AL = ARR_A;
    constexpr int OFF_BH = 2 * ARR_A;
    constexpr int OFF_BL = 2 * ARR_A + ARR_B;
    constexpr int BUFB   = 2 * ARR_A + 2 * ARR_B;
    constexpr int NTXN   = 512 + TN * 16;      // 16B txns per chunk
    constexpr int NT_PER_W = DH / TN;          // n-tiles per weight

    extern __shared__ char sm[];
    const uint32_t sbase = smem_u32(sm);
    const int tid  = threadIdx.x;
    const int warp = tid >> 5, lane = tid & 31;
    const int grp  = lane >> 2, tig = lane & 3;
    const int wn   = warp * (TN / 4);          // warp N offset

    const int m0 = blockIdx.x * 32;
    int n0, widx, region = 0;
    if (MODE == 1) {
        region = blockIdx.y / NT_PER_W;
        n0 = (blockIdx.y % NT_PER_W) * TN;
        widx = 1 + region;
    } else {
        n0 = blockIdx.y * TN; widx = (MODE == 0) ? 0 : 4;
    }

    const __nv_bfloat16* __restrict__ Ah = (MODE == 0) ? g_xhi : g_Ahi;
    const __nv_bfloat16* __restrict__ Al = (MODE == 0) ? g_xlo : g_Alo;
    const __nv_bfloat16* __restrict__ Bh = g_Wthi + (size_t)widx * DH * DH;
    const __nv_bfloat16* __restrict__ Bl = g_Wtlo + (size_t)widx * DH * DH;

    // ---- async loader: chunk c (64 k) into buffer buf ----
    auto issue = [&](int c, int buf) {
        #pragma unroll
        for (int i = 0; i < NTXN / 128; ++i) {
            const int idx = tid + i * 128;
            const __nv_bfloat16* gp;
            uint32_t sa;
            if (idx < 512) {                       // A: Ah then Al, 256 txns each
                const int arr = idx >> 8;          // 0:Ah 1:Al
                const int row = (idx & 255) >> 3;
                const int kv  = (idx & 7) * 8;
                gp = (arr == 0 ? Ah : Al) + (size_t)(m0 + row) * DH + c * 64 + kv;
                sa = sbase + buf * BUFB + arr * OFF_AL + row * ROWB + kv * 2;
            } else {                               // B: Bh then Bl, TN*8 txns each
                const int j   = idx - 512;
                const int arr = j / (TN * 8);      // 0:Bh 1:Bl
                const int rj  = j - arr * (TN * 8);
                const int row = rj >> 3;
                const int kv  = (rj & 7) * 8;
                gp = (arr == 0 ? Bh : Bl) + (size_t)(n0 + row) * DH + c * 64 + kv;
                sa = sbase + buf * BUFB + (arr == 0 ? OFF_BH : OFF_BL) + row * ROWB + kv * 2;
            }
            cp_async16(sa, gp);
        }
        cp_commit();
    };

    float acc[2][NAT][4] = {};   // [matom][natom][reg]

    auto compute = [&](int buf) {
        const char* base = sm + buf * BUFB;
        const char* A0 = base;
        const char* A1 = base + OFF_AL;
        const char* B0 = base + OFF_BH;
        const char* B1 = base + OFF_BL;
        #pragma unroll
        for (int ks = 0; ks < 4; ++ks) {
            const int kb = ks * 16 + 2 * tig;
            uint32_t ah[2][4], al[2][4], bh[NAT][2], bl[NAT][2];
            #pragma unroll
            for (int ma = 0; ma < 2; ++ma) {
                const int r = ma * 16 + grp;
                ah[ma][0] = *(const uint32_t*)(A0 + r * ROWB + kb * 2);
                ah[ma][1] = *(const uint32_t*)(A0 + (r + 8) * ROWB + kb * 2);
                ah[ma][2] = *(const uint32_t*)(A0 + r * ROWB + (kb + 8) * 2);
                ah[ma][3] = *(const uint32_t*)(A0 + (r + 8) * ROWB + (kb + 8) * 2);
                al[ma][0] = *(const uint32_t*)(A1 + r * ROWB + kb * 2);
                al[ma][1] = *(const uint32_t*)(A1 + (r + 8) * ROWB + kb * 2);
                al[ma][2] = *(const uint32_t*)(A1 + r * ROWB + (kb + 8) * 2);
                al[ma][3] = *(const uint32_t*)(A1 + (r + 8) * ROWB + (kb + 8) * 2);
            }
            #pragma unroll
            for (int nb = 0; nb < NAT; ++nb) {
                const int r = wn + nb * 8 + grp;
                bh[nb][0] = *(const uint32_t*)(B0 + r * ROWB + kb * 2);
                bh[nb][1] = *(const uint32_t*)(B0 + r * ROWB + (kb + 8) * 2);
                bl[nb][0] = *(const uint32_t*)(B1 + r * ROWB + kb * 2);
                bl[nb][1] = *(const uint32_t*)(B1 + r * ROWB + (kb + 8) * 2);
            }
            #pragma unroll
            for (int ma = 0; ma < 2; ++ma)
                #pragma unroll
                for (int nb = 0; nb < NAT; ++nb) {
                    mma_bf16(acc[ma][nb], ah[ma], bh[nb]);
                    mma_bf16(acc[ma][nb], ah[ma], bl[nb]);
                    mma_bf16(acc[ma][nb], al[ma], bh[nb]);
                }
        }
    };

    // ---- pipelined K loop ----
    issue(0, 0);
    cp_wait0();
    __syncthreads();
    #pragma unroll 1
    for (int c = 0; c < 8; ++c) {
        if (c < 7) issue(c + 1, (c + 1) & 1);
        compute(c & 1);
        if (c < 7) { cp_wait0(); __syncthreads(); }
    }

    // ---- fused epilogue ----
    #pragma unroll
    for (int ma = 0; ma < 2; ++ma) {
        #pragma unroll
        for (int nb = 0; nb < NAT; ++nb) {
            const float* d = acc[ma][nb];
            const int col = n0 + wn + nb * 8 + 2 * tig;
            #pragma unroll
            for (int half = 0; half < 2; ++half) {
                const int row = m0 + ma * 16 + grp + half * 8;
                const float v0 = d[half * 2 + 0];
                const float v1 = d[half * 2 + 1];
                const size_t idx = (size_t)row * DH + col;
                if (MODE == 0) {
                    const float s0 = v0 + b0v[col], s1 = v1 + b0v[col + 1];
                    const float r0 = s0 > 0.f ? s0 : expm1f(s0);
                    const float r1 = s1 > 0.f ? s1 : expm1f(s1);
                    g_rep[idx] = r0; g_rep[idx + 1] = r1;
                    __nv_bfloat16 h, l;
                    split_bf16(r0, h, l); g_Ahi[idx]     = h; g_Alo[idx]     = l;
                    split_bf16(r1, h, l); g_Ahi[idx + 1] = h; g_Alo[idx + 1] = l;
                } else if (MODE == 1) {
                    if (region == 0) {
                        // packed (dep', rep): dep' = (dep + w1_b + b_logit)/C
                        g_dr[idx]     = make_float2((v0 + b0v[col]     + b2v[col])     * INVC, g_rep[idx]);
                        g_dr[idx + 1] = make_float2((v1 + b0v[col + 1] + b2v[col + 1]) * INVC, g_rep[idx + 1]);
                    } else if (region == 1) {
                        g_head2[idx]     = (v0 + b1v[col])     * INVC;
                        g_head2[idx + 1] = (v1 + b1v[col + 1]) * INVC;
                    } else {
                        g_gate1[idx] = v0; g_gate1[idx + 1] = v1;
                    }
                } else {
                    const float z0 = g_gate1[idx]     + v0 + b0v[col];
                    const float z1 = g_gate1[idx + 1] + v1 + b0v[col + 1];
                    const float gg0 = 1.f / (1.f + expf(-z0));
                    const float gg1 = 1.f / (1.f + expf(-z1));
                    const float a0 = g_attn[idx], a1 = g_attn[idx + 1];
                    dout[idx]     = fmaf(gg0, g_rep[idx]     - a0, a0);
                    dout[idx + 1] = fmaf(gg1, g_rep[idx + 1] - a1, a1);
                }
            }
        }
    }
}

#define SMTOT32 (2 * (4 * 32 * ROWB))                   // 36864
#define SMTOT64 (2 * (2 * 32 * ROWB + 2 * 64 * ROWB))   // 55296

// =====================================================================
// Attention partials: 4 head-rows per CTA x 4 j-quarters.
// grid (130, 4, 2): x -> (batch, group q), y -> j-quarter, z -> ch half.
// q<63: rows {a=2q, a+1, c=253-2q, c+1} share each (dep', rep) load; per-
//   thread wfun count is exactly 512 per full group (balanced across q).
//   Window [a+1, 256) quartered; row activation thresholds (a+2, c+1, c+2)
//   clamped into the quarter -> 4 branch-free segment loops.
// q=63: rows {126,127,128}. q=64: row 255, FULLY masked: the reference's
//   logits+(-1e9) round to exactly -1e9 in fp32 -> softmax exactly uniform
//   -> partial (sum rep, count).
// Combine kernel: attn = (sum n_y) / (sum d_y), + bf16 split.
// =====================================================================
__device__ __forceinline__ float wtanh(float v) {
    return ex2f(C2CNST * tanh_ap(v));
}
__device__ __forceinline__ void store_attn(int idx, float v) {
    g_attn[idx] = v;
    __nv_bfloat16 hi, lo; split_bf16(v, hi, lo);
    g_Ahi[idx] = hi; g_Alo[idx] = lo;
}
__device__ __forceinline__ int clampi(int v, int lo, int hi) {
    return v < lo ? lo : (v > hi ? hi : v);
}

__global__ void __launch_bounds__(256) attn_part()
{
    const int cta = blockIdx.x;
    const int b = cta / 65;
    const int q = cta - b * 65;
    const int y = blockIdx.y;                      // j-quarter
    const int h = blockIdx.z * 256 + threadIdx.x;  // channel
    const int rb = b * LSEQ;

    const float2* __restrict__ dr = g_dr    + rb * DH;
    const float*  __restrict__ hd = g_head2 + rb * DH;

    if (q == 64) {
        // Row 255: uniform mean; quarter partial = (sum rep over 64 j, 64).
        float s = 0.f;
        const float2* pj = dr + (y * 64) * DH + h;
        #pragma unroll 8
        for (int j = 0; j < 64; ++j, pj += DH)
            s += pj->y;
        g_part[y][(rb + 255) * DH + h] = make_float2(s, 64.f);
        return;
    }

    if (q == 63) {
        // rows 126,127,128; window [127,256), W=129
        const int w0 = 127 + (129 * y) / 4;
        const int w1 = 127 + (129 * (y + 1)) / 4;
        const int s1 = clampi(128, w0, w1);
        const int s2 = clampi(129, w0, w1);
        const float h0 = hd[126 * DH + h];
        const float h1 = hd[127 * DH + h];
        const float h2 = hd[128 * DH + h];
        float n0 = 0.f, d0 = 0.f, n1 = 0.f, d1 = 0.f, n2 = 0.f, d2 = 0.f;
        const float2* pj = dr + (size_t)w0 * DH + h;
        int j = w0;
        for (; j < s1; ++j, pj += DH) {
            const float2 v = *pj;
            const float w = wtanh(v.x + h0); n0 = fmaf(w, v.y, n0); d0 += w;
        }
        for (; j < s2; ++j, pj += DH) {
            const float2 v = *pj;
            float w = wtanh(v.x + h0); n0 = fmaf(w, v.y, n0); d0 += w;
            w = wtanh(v.x + h1); n1 = fmaf(w, v.y, n1); d1 += w;
        }
        #pragma unroll 2
        for (; j < w1; ++j, pj += DH) {
            const float2 v = *pj;
            float w = wtanh(v.x + h0); n0 = fmaf(w, v.y, n0); d0 += w;
            w = wtanh(v.x + h1); n1 = fmaf(w, v.y, n1); d1 += w;
            w = wtanh(v.x + h2); n2 = fmaf(w, v.y, n2); d2 += w;
        }
        g_part[y][(rb + 126) * DH + h] = make_float2(n0, d0);
        g_part[y][(rb + 127) * DH + h] = make_float2(n1, d1);
        g_part[y][(rb + 128) * DH + h] = make_float2(n2, d2);
        return;
    }

    // rows a=2q, a+1, c=253-2q, c+1; window [a+1, 256)
    const int ra = 2 * q, rc = 253 - 2 * q;
    const int jstart = ra + 1;
    const int W = 255 - ra;
    const int w0 = jstart + (W * y) / 4;
    const int w1 = jstart + (W * (y + 1)) / 4;
    const int s1 = clampi(ra + 2, w0, w1);   // row a+1 activation
    const int s2 = clampi(rc + 1, w0, w1);   // row c activation
    const int s3 = clampi(rc + 2, w0, w1);   // row c+1 activation

    const float ha0 = hd[ra * DH + h];
    const float ha1 = hd[(ra + 1) * DH + h];
    const float hc0 = hd[rc * DH + h];
    const float hc1 = hd[(rc + 1) * DH + h];

    float na0 = 0.f, da0 = 0.f, na1 = 0.f, da1 = 0.f;
    float nc0 = 0.f, dc0 = 0.f, nc1 = 0.f, dc1 = 0.f;

    const float2* pj = dr + (size_t)w0 * DH + h;
    int j = w0;
    for (; j < s1; ++j, pj += DH) {          // row a only
        const float2 v = *pj;
        const float w = wtanh(v.x + ha0); na0 = fmaf(w, v.y, na0); da0 += w;
    }
    #pragma unroll 2
    for (; j < s2; ++j, pj += DH) {          // rows a, a+1
        const float2 v = *pj;
        float w = wtanh(v.x + ha0); na0 = fmaf(w, v.y, na0); da0 += w;
        w = wtanh(v.x + ha1); na1 = fmaf(w, v.y, na1); da1 += w;
    }
    for (; j < s3; ++j, pj += DH) {          // rows a, a+1, c
        const float2 v = *pj;
        float w = wtanh(v.x + ha0); na0 = fmaf(w, v.y, na0); da0 += w;
        w = wtanh(v.x + ha1); na1 = fmaf(w, v.y, na1); da1 += w;
        w = wtanh(v.x + hc0); nc0 = fmaf(w, v.y, nc0); dc0 += w;
    }
    #pragma unroll 2
    for (; j < w1; ++j, pj += DH) {          // all 4 rows
        const float2 v = *pj;
        float w = wtanh(v.x + ha0); na0 = fmaf(w, v.y, na0); da0 += w;
        w = wtanh(v.x + ha1); na1 = fmaf(w, v.y, na1); da1 += w;
        w = wtanh(v.x + hc0); nc0 = fmaf(w, v.y, nc0); dc0 += w;
        w = wtanh(v.x + hc1); nc1 = fmaf(w, v.y, nc1); dc1 += w;
    }
    g_part[y][(rb + ra)     * DH + h] = make_float2(na0, da0);
    g_part[y][(rb + ra + 1) * DH + h] = make_float2(na1, da1);
    g_part[y][(rb + rc)     * DH + h] = make_float2(nc0, dc0);
    g_part[y][(rb + rc + 1) * DH + h] = make_float2(nc1, dc1);
}

__global__ void __launch_bounds__(256) attn_combine()
{
    const int idx = blockIdx.x * 256 + threadIdx.x;
    const float2 p0 = g_part[0][idx];
    const float2 p1 = g_part[1][idx];
    const float2 p2 = g_part[2][idx];
    const float2 p3 = g_part[3][idx];
    store_attn(idx, ((p0.x + p1.x) + (p2.x + p3.x)) / ((p0.y + p1.y) + (p2.y + p3.y)));
}

// =====================================================================
extern "C" void kernel_launch(void* const* d_in, const int* in_sizes, int n_in,
                              void* d_out, int out_size)
{
    const float* x       = (const float*)d_in[0];
    const float* fc_w    = (const float*)d_in[1];
    const float* fc_b    = (const float*)d_in[2];
    const float* w1_w    = (const float*)d_in[3];
    const float* w1_b    = (const float*)d_in[4];
    const float* w2_w    = (const float*)d_in[5];
    const float* w2_b    = (const float*)d_in[6];
    const float* b_logit = (const float*)d_in[7];
    const float* wf1_w   = (const float*)d_in[8];
    const float* wf2_w   = (const float*)d_in[9];
    const float* bf      = (const float*)d_in[10];
    float* out = (float*)d_out;

    cudaFuncSetAttribute((const void*)gemm_mma<0,32>, cudaFuncAttributeMaxDynamicSharedMemorySize, SMTOT32);
    cudaFuncSetAttribute((const void*)gemm_mma<1,64>, cudaFuncAttributeMaxDynamicSharedMemorySize, SMTOT64);
    cudaFuncSetAttribute((const void*)gemm_mma<2,32>, cudaFuncAttributeMaxDynamicSharedMemorySize, SMTOT32);

    // 0) weight transpose+split (z=0..4) and x split (z=5)
    prep_kernel<<<dim3(16, 16, 6), 256>>>(fc_w, w1_w, w2_w, wf1_w, wf2_w, x);
    // 1) rep = elu(x @ fc_w + fc_b)   (+ bf16 split of rep)  — 256 CTAs
    gemm_mma<0,32><<<dim3(16, 16), 128, SMTOT32>>>(fc_b, nullptr, nullptr, nullptr);
    // 2) dr/head2/gate1 = rep @ {w1,w2,wf1}                  — 384 CTAs
    gemm_mma<1,64><<<dim3(16, 24), 128, SMTOT64>>>(w1_b, w2_b, b_logit, nullptr);
    // 3) attention partials (1040 CTAs) + combine
    attn_part<<<dim3(130, 4, 2), 256>>>();
    attn_combine<<<MTOT * DH / 256, 256>>>();
    // 4) out = sigmoid(gate1 + attn@wf2 + bf) * rep + (1-g) * attn — 256 CTAs
    gemm_mma<2,32><<<dim3(16, 16), 128, SMTOT32>>>(bf, nullptr, nullptr, out);
}